// round 2
// baseline (speedup 1.0000x reference)
#include <cuda_runtime.h>

// RandomShiftsAug on GB300.
// Mathematical reduction: integer shifts + pixel-center grid => bilinear weights
// collapse to {1,0}; the op is out[n,c,y,x] = in[n,c, clamp(y+sy-4), clamp(x+sx-4)].
// Pure HBM-bound shifted copy: 302 MB in + 302 MB out.

#define PADV 4
#define NB   512
#define CB   9
#define HB   128
// float4 groups per image row = 128/4 = 32
// total float4 elements = 512*9*128*32 = 18,874,368
#define TOTAL4 18874368

__global__ void __launch_bounds__(256)
random_shift_copy_kernel(const float* __restrict__ x,
                         const int* __restrict__ shift,
                         float* __restrict__ out)
{
    int idx4 = blockIdx.x * blockDim.x + threadIdx.x;
    if (idx4 >= TOTAL4) return;

    int xq = (idx4 & 31) << 2;   // starting output column (0..124, step 4)
    int t  = idx4 >> 5;
    int y  = t & (HB - 1);       // output row
    int nc = t >> 7;             // n*9 + c
    int n  = nc / CB;

    // shift layout [512,1,1,2]: (sx, sy) per n
    int sx = shift[2 * n]     - PADV;
    int sy = shift[2 * n + 1] - PADV;

    int ys = y + sy;
    ys = ys < 0 ? 0 : (ys > HB - 1 ? HB - 1 : ys);

    const float* __restrict__ row = x + ((long long)nc * HB + ys) * HB;

    int c0 = xq + 0 + sx; c0 = c0 < 0 ? 0 : (c0 > HB - 1 ? HB - 1 : c0);
    int c1 = xq + 1 + sx; c1 = c1 < 0 ? 0 : (c1 > HB - 1 ? HB - 1 : c1);
    int c2 = xq + 2 + sx; c2 = c2 < 0 ? 0 : (c2 > HB - 1 ? HB - 1 : c2);
    int c3 = xq + 3 + sx; c3 = c3 < 0 ? 0 : (c3 > HB - 1 ? HB - 1 : c3);

    float4 v;
    v.x = __ldg(row + c0);
    v.y = __ldg(row + c1);
    v.z = __ldg(row + c2);
    v.w = __ldg(row + c3);

    reinterpret_cast<float4*>(out)[idx4] = v;
}

extern "C" void kernel_launch(void* const* d_in, const int* in_sizes, int n_in,
                              void* d_out, int out_size)
{
    const float* x     = (const float*)d_in[0];
    const int*   shift = (const int*)d_in[1];
    float*       out   = (float*)d_out;

    const int threads = 256;
    const int blocks  = (TOTAL4 + threads - 1) / threads;  // 73728
    random_shift_copy_kernel<<<blocks, threads>>>(x, shift, out);
}